// round 15
// baseline (speedup 1.0000x reference)
#include <cuda_runtime.h>
#include <cuda_bf16.h>
#include <cstdint>
#include <math.h>

// ---------------- model constants ----------------
#define TT 2048
#define BB 2
#define SS 1024
#define DD 1024
#define HH 16
#define KVH 4
#define HDIM 64
#define LL 4
#define EE 8
#define FF 1024
#define VV 32000
#define CAP 4096
#define QD (HH*HDIM)   // 1024
#define KD (KVH*HDIM)  // 256
#define ATT_SCALE 0.125f
#define RMS_EPS 1e-6f
#define ROPE_L2 (-0.62286151779138045f)   // -log2(1e6)/32

// ---------------- plane sizes (pairs) ----------------
constexpr long P_H    = (long)TT*DD/2;
constexpr long P_Q    = (long)TT*QD/2;
constexpr long P_K    = (long)TT*KD/2;
constexpr long P_O    = (long)TT*QD/2;
constexpr long P_GTS  = (long)TT*FF;        // 2*TT*FF/2
constexpr long P_SC   = (long)BB*HH*SS*SS/2;
constexpr long P_EMB  = (long)VV*DD/2;
constexpr long P_WQ   = (long)LL*DD*QD/2;
constexpr long P_WK   = (long)LL*DD*KD/2;
constexpr long P_WO   = (long)LL*QD*DD/2;
constexpr long P_GATE = (long)LL*EE*DD*FF/2;

// ---------------- scratch ----------------
__device__ float    g_x[TT*DD];
__device__ float    g_q[TT*QD];
__device__ float    g_k[TT*KD];
__device__ float    g_scores[(long)BB*HH*SS*SS];
__device__ float    g_gate[2*TT*FF];
__device__ float    g_up[2*TT*FF];
__device__ float    g_y[2*TT*DD];
__device__ float    g_rlog[TT*EE];
__device__ float    g_pairw[2*TT];
__device__ int      g_cnt[EE];
__device__ int      g_ptok[EE*CAP];
__device__ int      g_ppair[EE*CAP];
// split (u32 pair) buffers: [0..P)=hi, [P..2P)=lo
__device__ uint32_t g_h_s[2*P_H];
__device__ uint32_t g_q_s[2*P_Q];
__device__ uint32_t g_k_s[2*P_K];
__device__ uint32_t g_v_s[2*P_K];
__device__ uint32_t g_o_s[2*P_O];
__device__ uint32_t g_gts_s[2*P_GTS];
__device__ uint32_t g_sc_s[2*P_SC];
__device__ uint32_t g_emb_s[2*P_EMB];
__device__ uint32_t g_wq_s[2*P_WQ];
__device__ uint32_t g_wk_s[2*P_WK];
__device__ uint32_t g_wv_s[2*P_WK];
__device__ uint32_t g_wo_s[2*P_WO];
__device__ uint32_t g_gate_s[2*P_GATE];
__device__ uint32_t g_up_s[2*P_GATE];
__device__ uint32_t g_down_s[2*P_GATE];

__device__ __forceinline__ float warpReduceSum(float v){
#pragma unroll
    for (int o = 16; o; o >>= 1) v += __shfl_xor_sync(0xffffffffu, v, o);
    return v;
}

__device__ __forceinline__ void split_pack(float x0, float x1, uint32_t& h, uint32_t& l){
    __nv_bfloat16 h0 = __float2bfloat16(x0);
    __nv_bfloat16 h1 = __float2bfloat16(x1);
    __nv_bfloat16 l0 = __float2bfloat16(x0 - __bfloat162float(h0));
    __nv_bfloat16 l1 = __float2bfloat16(x1 - __bfloat162float(h1));
    __nv_bfloat162 hh = __halves2bfloat162(h0, h1);
    __nv_bfloat162 ll = __halves2bfloat162(l0, l1);
    h = *reinterpret_cast<uint32_t*>(&hh);
    l = *reinterpret_cast<uint32_t*>(&ll);
}

__device__ __forceinline__ uint32_t smem_u32addr(const void* p){
    return (uint32_t)__cvta_generic_to_shared(p);
}

// ---------------- conversion: fp32 -> split pair planes ----------------
__global__ void convert_split(const float* __restrict__ in, uint32_t* __restrict__ out, long nP)
{
    long i = (long)blockIdx.x * blockDim.x + threadIdx.x;   // 2 pairs each
    if (i*2 >= nP) return;
    float4 v = *reinterpret_cast<const float4*>(in + i*4);
    uint32_t h0,l0,h1,l1;
    split_pack(v.x, v.y, h0, l0);
    split_pack(v.z, v.w, h1, l1);
    *reinterpret_cast<uint2*>(&out[i*2])      = make_uint2(h0,h1);
    *reinterpret_cast<uint2*>(&out[nP + i*2]) = make_uint2(l0,l1);
}

// ============== bf16x2 (3-product) mma GEMM, pre-split inputs ==============
constexpr int BM = 128, BN = 128, BK = 16;
constexpr int SAK  = 12;
constexpr int BST  = 68;
constexpr int PLSZ = 1536;
constexpr int PLB  = PLSZ*4;

#define MMAB(d, a, b) \
  asm volatile("mma.sync.aligned.m16n8k16.row.col.f32.bf16.bf16.f32 " \
    "{%0,%1,%2,%3},{%4,%5,%6,%7},{%8,%9},{%0,%1,%2,%3};" \
    : "+f"(d[0]),"+f"(d[1]),"+f"(d[2]),"+f"(d[3]) \
    : "r"(a[0]),"r"(a[1]),"r"(a[2]),"r"(a[3]),"r"(b[0]),"r"(b[1]))

#define LDSM4(R, A) \
  asm volatile("ldmatrix.sync.aligned.m8n8.x4.shared.b16 {%0,%1,%2,%3},[%4];" \
    : "=r"((R)[0]),"=r"((R)[1]),"=r"((R)[2]),"=r"((R)[3]) : "r"(A))
#define LDSM4T(R0,R1,R2,R3, A) \
  asm volatile("ldmatrix.sync.aligned.m8n8.x4.trans.shared.b16 {%0,%1,%2,%3},[%4];" \
    : "=r"(R0),"=r"(R1),"=r"(R2),"=r"(R3) : "r"(A))

// OUT: 0=store fp32, 1=add fp32, 2=store split pairs
template<bool TB, int OUT, bool GATHER>
__device__ __forceinline__ void mma_body(
    const uint32_t* __restrict__ Ah, long aP, long aBase, int ldaP,
    const uint32_t* __restrict__ Bh, long bP, long bBase, int ldbP,
    float* __restrict__ C, int ldc,
    uint32_t* __restrict__ Cs, long cP, long cBase, int ldcP,
    int M, int N, int K, int m0, int n0, float alpha,
    const int* __restrict__ aidx, const int* __restrict__ cidx)
{
    __shared__ uint32_t sA[2][2][PLSZ];
    __shared__ uint32_t sB[2][2][PLSZ];
    const int tid = threadIdx.x;
    const int lane = tid & 31, wid = tid >> 5;
    const int wm = wid & 1, wn = wid >> 1;
    const int g = lane >> 2, tq = lane & 3;

    float acc[4][4][4];
#pragma unroll
    for (int mt=0; mt<4; mt++)
#pragma unroll
        for (int nt=0; nt<4; nt++)
#pragma unroll
            for (int i=0;i<4;i++) acc[mt][nt][i]=0.f;

    // ---- global mappings (pairs) ----
    bool aok[2]; long aG[2]; int aS[2];
#pragma unroll
    for (int i=0;i<2;i++){
        int idx = tid + i*256;
        int row = idx>>2, pp=(idx&3)*2;
        int m = m0 + row;
        aok[i] = m < M;
        int r = aok[i] ? (GATHER ? aidx[m] : m) : 0;
        aG[i] = aBase + (long)r*ldaP + pp;
        aS[i] = row*SAK + pp;
    }
    bool bok = false; long bG = 0; int bS0=0, bS1=0;
    bool btok[2]; long bGT[2]; int bST[2];
    if (!TB){
        int kp = tid >> 5;
        int np = (tid & 31)*2;
        bok = (n0 + (tid&31)*4) < N;
        bG  = bBase + (long)(2*kp)*ldbP + n0/2 + np;
        bS0 = (2*kp)*BST + np;
        bS1 = bS0 + BST;
    } else {
#pragma unroll
        for (int i=0;i<2;i++){
            int idx = tid + i*256;
            int n = idx>>2, pp=(idx&3)*2;
            btok[i] = (n0+n) < N;
            bGT[i]  = bBase + (long)(n0+n)*ldbP + pp;
            bST[i]  = n*SAK + pp;
        }
    }

    // ---- ldmatrix fragment offsets ----
    const int lx = lane & 7;
    const int aFragOff  = ((wm*64 + lx + ((lane>>3)&1)*8)*SAK + ((lane>>4)&1)*4)*4;
    const int bFragOffT = ((wn*32 + lx + ((lane>>4)&1)*8)*SAK + ((lane>>3)&1)*4)*4;
    const int bFragOffN = ((lx + ((lane>>3)&1)*8)*BST + wn*16 + ((lane>>4)&1)*4)*4;

    const uint2 Z2 = make_uint2(0,0);

    // ---- prologue ----
#pragma unroll
    for (int i=0;i<2;i++){
        uint2 h = aok[i] ? *reinterpret_cast<const uint2*>(&Ah[aG[i]]) : Z2;
        uint2 l = aok[i] ? *reinterpret_cast<const uint2*>(&Ah[aP + aG[i]]) : Z2;
        *reinterpret_cast<uint2*>(&sA[0][0][aS[i]]) = h;
        *reinterpret_cast<uint2*>(&sA[0][1][aS[i]]) = l;
    }
    if (!TB){
        uint2 h0 = bok ? *reinterpret_cast<const uint2*>(&Bh[bG]) : Z2;
        uint2 l0 = bok ? *reinterpret_cast<const uint2*>(&Bh[bP + bG]) : Z2;
        uint2 h1 = bok ? *reinterpret_cast<const uint2*>(&Bh[bG + ldbP]) : Z2;
        uint2 l1 = bok ? *reinterpret_cast<const uint2*>(&Bh[bP + bG + ldbP]) : Z2;
        *reinterpret_cast<uint2*>(&sB[0][0][bS0]) = h0;
        *reinterpret_cast<uint2*>(&sB[0][1][bS0]) = l0;
        *reinterpret_cast<uint2*>(&sB[0][0][bS1]) = h1;
        *reinterpret_cast<uint2*>(&sB[0][1][bS1]) = l1;
    } else {
#pragma unroll
        for (int i=0;i<2;i++){
            uint2 h = btok[i] ? *reinterpret_cast<const uint2*>(&Bh[bGT[i]]) : Z2;
            uint2 l = btok[i] ? *reinterpret_cast<const uint2*>(&Bh[bP + bGT[i]]) : Z2;
            *reinterpret_cast<uint2*>(&sB[0][0][bST[i]]) = h;
            *reinterpret_cast<uint2*>(&sB[0][1][bST[i]]) = l;
        }
    }
    __syncthreads();

    const int nk = K / BK;
    for (int kb = 0; kb < nk; kb++){
        const int cur = kb & 1;
        uint2 pah[2], pal[2], pbh0, pbl0, pbh1, pbl1, pth[2], ptl[2];
        if (kb+1 < nk){
#pragma unroll
            for (int i=0;i<2;i++){
                long o = aG[i] + (long)(kb+1)*8;
                pah[i] = aok[i] ? *reinterpret_cast<const uint2*>(&Ah[o]) : Z2;
                pal[i] = aok[i] ? *reinterpret_cast<const uint2*>(&Ah[aP + o]) : Z2;
            }
            if (!TB){
                long o = bG + (long)(kb+1)*16*ldbP;
                pbh0 = bok ? *reinterpret_cast<const uint2*>(&Bh[o]) : Z2;
                pbl0 = bok ? *reinterpret_cast<const uint2*>(&Bh[bP + o]) : Z2;
                pbh1 = bok ? *reinterpret_cast<const uint2*>(&Bh[o + ldbP]) : Z2;
                pbl1 = bok ? *reinterpret_cast<const uint2*>(&Bh[bP + o + ldbP]) : Z2;
            } else {
#pragma unroll
                for (int i=0;i<2;i++){
                    long o = bGT[i] + (long)(kb+1)*8;
                    pth[i] = btok[i] ? *reinterpret_cast<const uint2*>(&Bh[o]) : Z2;
                    ptl[i] = btok[i] ? *reinterpret_cast<const uint2*>(&Bh[bP + o]) : Z2;
                }
            }
        }

        // ---- fragments ----
        uint32_t ah[4][4], al[4][4], bh[4][2], bl[4][2];
        {
            uint32_t aH = smem_u32addr(&sA[cur][0][0]) + aFragOff;
#pragma unroll
            for (int mt=0; mt<4; mt++){
                LDSM4(ah[mt], aH + mt*(16*SAK*4));
                LDSM4(al[mt], aH + mt*(16*SAK*4) + PLB);
            }
            if (!TB){
                uint32_t bH = smem_u32addr(&sB[cur][0][0]) + bFragOffN;
#pragma unroll
                for (int ntp=0; ntp<2; ntp++){
                    LDSM4T(bh[2*ntp][0], bh[2*ntp][1], bh[2*ntp+1][0], bh[2*ntp+1][1],
                           bH + ntp*32);
                    LDSM4T(bl[2*ntp][0], bl[2*ntp][1], bl[2*ntp+1][0], bl[2*ntp+1][1],
                           bH + ntp*32 + PLB);
                }
            } else {
                uint32_t bH = smem_u32addr(&sB[cur][0][0]) + bFragOffT;
#pragma unroll
                for (int ntp=0; ntp<2; ntp++){
                    uint32_t R[4];
                    LDSM4(R, bH + ntp*(16*SAK*4));
                    bh[2*ntp][0]=R[0]; bh[2*ntp][1]=R[1]; bh[2*ntp+1][0]=R[2]; bh[2*ntp+1][1]=R[3];
                    LDSM4(R, bH + ntp*(16*SAK*4) + PLB);
                    bl[2*ntp][0]=R[0]; bl[2*ntp][1]=R[1]; bl[2*ntp+1][0]=R[2]; bl[2*ntp+1][1]=R[3];
                }
            }
        }
#pragma unroll
        for (int mt=0; mt<4; mt++)
#pragma unroll
            for (int nt=0; nt<4; nt++){
                MMAB(acc[mt][nt], al[mt], bh[nt]);
                MMAB(acc[mt][nt], ah[mt], bl[nt]);
                MMAB(acc[mt][nt], ah[mt], bh[nt]);
            }

        if (kb+1 < nk){
            const int nxt = 1-cur;
#pragma unroll
            for (int i=0;i<2;i++){
                *reinterpret_cast<uint2*>(&sA[nxt][0][aS[i]]) = pah[i];
                *reinterpret_cast<uint2*>(&sA[nxt][1][aS[i]]) = pal[i];
            }
            if (!TB){
                *reinterpret_cast<uint2*>(&sB[nxt][0][bS0]) = pbh0;
                *reinterpret_cast<uint2*>(&sB[nxt][1][bS0]) = pbl0;
                *reinterpret_cast<uint2*>(&sB[nxt][0][bS1]) = pbh1;
                *reinterpret_cast<uint2*>(&sB[nxt][1][bS1]) = pbl1;
            } else {
#pragma unroll
                for (int i=0;i<2;i++){
                    *reinterpret_cast<uint2*>(&sB[nxt][0][bST[i]]) = pth[i];
                    *reinterpret_cast<uint2*>(&sB[nxt][1][bST[i]]) = ptl[i];
                }
            }
            __syncthreads();
        }
    }

    // ---- epilogue ----
#pragma unroll
    for (int mt=0; mt<4; mt++){
        int r0 = m0 + wm*64 + mt*16 + g;
        int r1 = r0 + 8;
#pragma unroll
        for (int rr=0; rr<2; rr++){
            int m = rr ? r1 : r0;
            if (m >= M) continue;
            long crow = GATHER ? (long)cidx[m] : (long)m;
#pragma unroll
            for (int nt=0; nt<4; nt++){
                int c0 = n0 + wn*32 + nt*8 + tq*2;
                if (c0 >= N) continue;
                float v0 = acc[mt][nt][rr*2+0]*alpha;
                float v1 = acc[mt][nt][rr*2+1]*alpha;
                if (OUT == 0){
                    *reinterpret_cast<float2*>(C + crow*ldc + c0) = make_float2(v0, v1);
                } else if (OUT == 1){
                    float* cp = C + crow*ldc;
                    cp[c0] += v0; cp[c0+1] += v1;
                } else {
                    uint32_t h, l;
                    split_pack(v0, v1, h, l);
                    long pidx = cBase + crow*ldcP + c0/2;
                    Cs[pidx] = h;
                    Cs[cP + pidx] = l;
                }
            }
        }
    }
}

template<bool TB, bool ADD>
__global__ void __launch_bounds__(256)
mma_gemm(const uint32_t* __restrict__ Ah, long aP, long aBase, int ldaP,
         const uint32_t* __restrict__ Bh, long bP, long bBase, int ldbP,
         float* __restrict__ C, int ldc, int M, int N, int K)
{
    mma_body<TB, ADD?1:0, false>(Ah,aP,aBase,ldaP, Bh,bP,bBase,ldbP, C,ldc,
                                 nullptr,0,0,0, M,N,K,
                                 blockIdx.y*BM, blockIdx.x*BN, 1.f, nullptr, nullptr);
}

// fused QKV: grid (12, TT/BM). x: 0-7 Q, 8-9 K, 10-11 V(split out)
__global__ void __launch_bounds__(256)
qkv_gemm(const uint32_t* __restrict__ h_s,
         const uint32_t* __restrict__ wq_s, const uint32_t* __restrict__ wk_s,
         const uint32_t* __restrict__ wv_s,
         long wqB, long wkB, long wvB,
         float* __restrict__ q, float* __restrict__ k, uint32_t* __restrict__ v_s)
{
    int bx = blockIdx.x;
    int m0 = blockIdx.y*BM;
    if (bx < 8)
        mma_body<false,0,false>(h_s,P_H,0,DD/2, wq_s,P_WQ,wqB,QD/2, q,QD,
                                nullptr,0,0,0, TT,QD,DD, m0, bx*128, 1.f, nullptr,nullptr);
    else if (bx < 10)
        mma_body<false,0,false>(h_s,P_H,0,DD/2, wk_s,P_WK,wkB,KD/2, k,KD,
                                nullptr,0,0,0, TT,KD,DD, m0, (bx-8)*128, 1.f, nullptr,nullptr);
    else
        mma_body<false,2,false>(h_s,P_H,0,DD/2, wv_s,P_WK,wvB,KD/2, nullptr,0,
                                v_s,P_K,0,KD/2, TT,KD,DD, m0, (bx-10)*128, 1.f, nullptr,nullptr);
}

__global__ void __launch_bounds__(256)
moe_gemm(const uint32_t* __restrict__ A, long aP, int ldaP,
         const uint32_t* __restrict__ Bh, long bP, long bLayerB, long bEStride, int ldbP,
         float* __restrict__ C, int ldc, int N, int K,
         const int* __restrict__ aidx, const int* __restrict__ cidx,
         const int* __restrict__ cnt)
{
    int e = blockIdx.z;
    int M = cnt[e];
    int m0 = blockIdx.y * BM;
    if (m0 >= M) return;
    mma_body<false,0,true>(A,aP,0,ldaP, Bh,bP, bLayerB + (long)e*bEStride, ldbP,
                           C,ldc, nullptr,0,0,0, M,N,K, m0, blockIdx.x*BN, 1.f,
                           aidx + e*CAP, cidx + e*CAP);
}

__global__ void __launch_bounds__(256)
attn_scores_mma(const uint32_t* __restrict__ q_s, const uint32_t* __restrict__ k_s,
                float* __restrict__ scores)
{
    int z = blockIdx.z;
    int b = z / HH, h = z % HH;
    int m0 = blockIdx.y * BM, n0 = blockIdx.x * BN;
    if (n0 >= m0 + BM) return;
    mma_body<true,0,false>(q_s, P_Q, ((long)b*SS*QD + h*HDIM)/2, QD/2,
                           k_s, P_K, ((long)b*SS*KD + (h>>2)*HDIM)/2, KD/2,
                           scores + (long)z*SS*SS, SS, nullptr,0,0,0,
                           SS, SS, HDIM, m0, n0, ATT_SCALE, nullptr, nullptr);
}

__global__ void __launch_bounds__(256)
attn_pv_mma(const uint32_t* __restrict__ sc_s, const uint32_t* __restrict__ v_s,
            uint32_t* __restrict__ o_s)
{
    int z = blockIdx.z;
    int b = z / HH, h = z % HH;
    int m0 = blockIdx.y * BM;
    mma_body<false,2,false>(sc_s, P_SC, (long)z*SS*(SS/2), SS/2,
                            v_s, P_K, ((long)b*SS*KD + (h>>2)*HDIM)/2, KD/2,
                            nullptr, 0,
                            o_s, P_O, ((long)b*SS*QD + h*HDIM)/2, QD/2,
                            SS, HDIM, m0+BM, m0, 0, 1.f, nullptr, nullptr);
}

// ---------------- elementwise / small kernels ----------------
__global__ void embed_kernel(const int* __restrict__ ids, const float* __restrict__ emb,
                             float* __restrict__ x)
{
    int t = blockIdx.x;
    long src = (long)ids[t] * DD;
    int d = threadIdx.x * 4;
    *reinterpret_cast<float4*>(x + (long)t*DD + d) =
        *reinterpret_cast<const float4*>(emb + src + d);
}

__global__ void rmsnorm_split(const float* __restrict__ in, const float* __restrict__ w,
                              uint32_t* __restrict__ out)
{
    int t = blockIdx.x;
    const float* row = in + (long)t * DD;
    int d = threadIdx.x * 4;
    float4 va = *reinterpret_cast<const float4*>(row + d);
    float ss = va.x*va.x + va.y*va.y + va.z*va.z + va.w*va.w;
    __shared__ float red[8];
    __shared__ float bc;
    ss = warpReduceSum(ss);
    if ((threadIdx.x & 31) == 0) red[threadIdx.x >> 5] = ss;
    __syncthreads();
    if (threadIdx.x == 0) {
        float s = 0.f;
#pragma unroll
        for (int i = 0; i < 8; i++) s += red[i];
        bc = rsqrtf(s / (float)DD + RMS_EPS);
    }
    __syncthreads();
    float r = bc;
    float4 wv = *reinterpret_cast<const float4*>(w + d);
    float4 ov;
    ov.x = va.x*r*wv.x; ov.y = va.y*r*wv.y;
    ov.z = va.z*r*wv.z; ov.w = va.w*r*wv.w;
    uint32_t h0,l0,h1,l1;
    split_pack(ov.x, ov.y, h0, l0);
    split_pack(ov.z, ov.w, h1, l1);
    long pb = (long)t*(DD/2) + d/2;
    *reinterpret_cast<uint2*>(&out[pb])       = make_uint2(h0,h1);
    *reinterpret_cast<uint2*>(&out[P_H + pb]) = make_uint2(l0,l1);
}

// fused rope+norm, writes split; warp owns elems (2*lane, 2*lane+1)
__global__ void qk_rope_split(const float* __restrict__ q, const float* __restrict__ k,
                              uint32_t* __restrict__ q_s, uint32_t* __restrict__ k_s,
                              const float* __restrict__ qnw, const float* __restrict__ knw,
                              const int* __restrict__ pos_ids)
{
    int gw = (blockIdx.x * blockDim.x + threadIdx.x) >> 5;
    int lane = threadIdx.x & 31;
    int t = gw / (HH + KVH);
    int hh = gw - t * (HH + KVH);
    if (t >= TT) return;
    const float* p;
    const float* nw;
    uint32_t* outp;
    long P, obase;
    if (hh < HH) { p = q + (long)t*QD + hh*HDIM; nw = qnw; outp = q_s; P = P_Q;
                   obase = ((long)t*QD + hh*HDIM)/2; }
    else         { p = k + (long)t*KD + (hh-HH)*HDIM; nw = knw; outp = k_s; P = P_K;
                   obase = ((long)t*KD + (hh-HH)*HDIM)/2; }
    int d0 = 2*lane, d1 = d0 + 1;
    float v0 = p[d0], v1 = p[d1];
    float ss = warpReduceSum(v0*v0 + v1*v1);
    float r = rsqrtf(ss / 64.f + RMS_EPS);
    v0 *= r * nw[d0];
    v1 *= r * nw[d1];
    float pos = (float)pos_ids[t];
    float f0 = exp2f(ROPE_L2 * (float)(d0 & 31));
    float f1 = exp2f(ROPE_L2 * (float)(d1 & 31));
    float c0, s0, c1, s1;
    sincosf(pos * f0, &s0, &c0);
    sincosf(pos * f1, &s1, &c1);
    float pv0 = __shfl_xor_sync(0xffffffffu, v0, 16);
    float pv1 = __shfl_xor_sync(0xffffffffu, v1, 16);
    float o0, o1;
    if (lane < 16){ o0 = v0*c0 - pv0*s0; o1 = v1*c1 - pv1*s1; }
    else          { o0 = v0*c0 + pv0*s0; o1 = v1*c1 + pv1*s1; }
    uint32_t h, l;
    split_pack(o0, o1, h, l);
    outp[obase + lane]     = h;
    outp[P + obase + lane] = l;
}

// softmax: fp32 in, split out
__global__ void softmax_split(const float* __restrict__ scores, uint32_t* __restrict__ out)
{
    long z = blockIdx.y;
    int i = blockIdx.x;
    const float* row = scores + (z * SS + i) * (long)SS;
    int valid = i + 1;
    int j0 = threadIdx.x * 4;
    float4 v = *reinterpret_cast<const float4*>(row + j0);
    __shared__ float red[8];
    __shared__ float bc;

    float m = -1e30f;
    if (j0+0 < valid) m = fmaxf(m, v.x);
    if (j0+1 < valid) m = fmaxf(m, v.y);
    if (j0+2 < valid) m = fmaxf(m, v.z);
    if (j0+3 < valid) m = fmaxf(m, v.w);
#pragma unroll
    for (int o = 16; o; o >>= 1) m = fmaxf(m, __shfl_xor_sync(0xffffffffu, m, o));
    if ((threadIdx.x & 31) == 0) red[threadIdx.x >> 5] = m;
    __syncthreads();
    if (threadIdx.x == 0) {
        float mm = -1e30f;
#pragma unroll
        for (int i2 = 0; i2 < 8; i2++) mm = fmaxf(mm, red[i2]);
        bc = mm;
    }
    __syncthreads();
    m = bc;

    float4 e;
    e.x = (j0+0 < valid) ? expf(v.x - m) : 0.f;
    e.y = (j0+1 < valid) ? expf(v.y - m) : 0.f;
    e.z = (j0+2 < valid) ? expf(v.z - m) : 0.f;
    e.w = (j0+3 < valid) ? expf(v.w - m) : 0.f;
    float s = e.x + e.y + e.z + e.w;
    s = warpReduceSum(s);
    if ((threadIdx.x & 31) == 0) red[threadIdx.x >> 5] = s;
    __syncthreads();
    if (threadIdx.x == 0) {
        float t = 0.f;
#pragma unroll
        for (int i2 = 0; i2 < 8; i2++) t += red[i2];
        bc = t;
    }
    __syncthreads();
    float inv = 1.f / bc;
    e.x *= inv; e.y *= inv; e.z *= inv; e.w *= inv;
    uint32_t h0,l0,h1,l1;
    split_pack(e.x, e.y, h0, l0);
    split_pack(e.z, e.w, h1, l1);
    long pb = (z * SS + i) * (long)(SS/2) + j0/2;
    *reinterpret_cast<uint2*>(&out[pb])        = make_uint2(h0,h1);
    *reinterpret_cast<uint2*>(&out[P_SC + pb]) = make_uint2(l0,l1);
}

__global__ void router_kernel(const uint32_t* __restrict__ h_s, const float* __restrict__ rw,
                              float* __restrict__ lg)
{
    int t = blockIdx.x;
    int w = threadIdx.x >> 5, lane = threadIdx.x & 31;
    long base = (long)t * (DD/2);
    float s = 0.f;
    for (int pd = lane; pd < DD/2; pd += 32){
        uint32_t hu = h_s[base + pd];
        uint32_t lu = h_s[P_H + base + pd];
        __nv_bfloat162 hb = *reinterpret_cast<__nv_bfloat162*>(&hu);
        __nv_bfloat162 lb = *reinterpret_cast<__nv_bfloat162*>(&lu);
        float e0 = __bfloat162float(hb.x) + __bfloat162float(lb.x);
        float e1 = __bfloat162float(hb.y) + __bfloat162float(lb.y);
        s += e0 * rw[(2*pd)*EE + w] + e1 * rw[(2*pd+1)*EE + w];
    }
    s = warpReduceSum(s);
    if (lane == 0) lg[t * EE + w] = s;
}

__global__ void assign_kernel(const float* __restrict__ lg, int* __restrict__ cnt,
                              int* __restrict__ ptok, int* __restrict__ ppair,
                              float* __restrict__ pw)
{
    int t = blockIdx.x * blockDim.x + threadIdx.x;
    if (t >= TT) return;
    float l1 = -1e30f, l2 = -1e30f;
    int i1 = 0, i2 = 0;
#pragma unroll
    for (int e = 0; e < EE; e++) {
        float v = lg[t * EE + e];
        if (v > l1) { l2 = l1; i2 = i1; l1 = v; i1 = e; }
        else if (v > l2) { l2 = v; i2 = e; }
    }
    float e2 = expf(l2 - l1);
    float w1 = 1.f / (1.f + e2);
    float w2 = e2 / (1.f + e2);
    int p = atomicAdd(&cnt[i1], 1);
    ptok[i1 * CAP + p] = t;  ppair[i1 * CAP + p] = 2 * t;
    p = atomicAdd(&cnt[i2], 1);
    ptok[i2 * CAP + p] = t;  ppair[i2 * CAP + p] = 2 * t + 1;
    pw[2 * t] = w1;  pw[2 * t + 1] = w2;
}

__global__ void silu_split(const float* __restrict__ g, const float* __restrict__ u,
                           uint32_t* __restrict__ out)
{
    long i = (long)blockIdx.x * blockDim.x + threadIdx.x;   // 4 elems
    long base = i * 4;
    float4 gv = *reinterpret_cast<const float4*>(g + base);
    float4 uv = *reinterpret_cast<const float4*>(u + base);
    float4 ov;
    ov.x = gv.x / (1.f + expf(-gv.x)) * uv.x;
    ov.y = gv.y / (1.f + expf(-gv.y)) * uv.y;
    ov.z = gv.z / (1.f + expf(-gv.z)) * uv.z;
    ov.w = gv.w / (1.f + expf(-gv.w)) * uv.w;
    uint32_t h0,l0,h1,l1;
    split_pack(ov.x, ov.y, h0, l0);
    split_pack(ov.z, ov.w, h1, l1);
    *reinterpret_cast<uint2*>(&out[base/2])         = make_uint2(h0,h1);
    *reinterpret_cast<uint2*>(&out[P_GTS + base/2]) = make_uint2(l0,l1);
}

__global__ void combine_kernel(float* __restrict__ x, const float* __restrict__ y,
                               const float* __restrict__ pw)
{
    int t = blockIdx.x;
    float w0 = pw[2 * t], w1 = pw[2 * t + 1];
    int d = threadIdx.x * 4;
    float4 a  = *reinterpret_cast<float4*>(x + (long)t*DD + d);
    float4 y0 = *reinterpret_cast<const float4*>(y + (long)(2*t)*DD + d);
    float4 y1 = *reinterpret_cast<const float4*>(y + (long)(2*t+1)*DD + d);
    a.x += w0*y0.x + w1*y1.x;
    a.y += w0*y0.y + w1*y1.y;
    a.z += w0*y0.z + w1*y1.z;
    a.w += w0*y0.w + w1*y1.w;
    *reinterpret_cast<float4*>(x + (long)t*DD + d) = a;
}

// ---------------- launch ----------------
extern "C" void kernel_launch(void* const* d_in, const int* in_sizes, int n_in,
                              void* d_out, int out_size)
{
    const int*   token_ids = (const int*)  d_in[0];
    const int*   pos_ids   = (const int*)  d_in[1];
    const float* tok_emb   = (const float*)d_in[2];
    const float* attn_norm = (const float*)d_in[3];
    const float* wq        = (const float*)d_in[4];
    const float* wk        = (const float*)d_in[5];
    const float* wv        = (const float*)d_in[6];
    const float* qn        = (const float*)d_in[7];
    const float* kn        = (const float*)d_in[8];
    const float* wo        = (const float*)d_in[9];
    const float* ffn_norm  = (const float*)d_in[10];
    const float* router_w  = (const float*)d_in[11];
    const float* gate_w    = (const float*)d_in[12];
    const float* up_w      = (const float*)d_in[13];
    const float* down_w    = (const float*)d_in[14];
    const float* fin_norm  = (const float*)d_in[15];

    float *x, *q, *k, *sc, *gt, *up, *y, *rlog, *pw;
    int *cnt, *ptok, *ppair;
    uint32_t *h_s, *q_s, *k_s, *v_s, *o_s, *gts_s, *sc_s;
    uint32_t *emb_s, *wq_s, *wk_s, *wv_s, *wo_s, *gate_s, *up_s, *down_s;
    cudaGetSymbolAddress((void**)&x,  g_x);
    cudaGetSymbolAddress((void**)&q,  g_q);
    cudaGetSymbolAddress((void**)&k,  g_k);
    cudaGetSymbolAddress((void**)&sc, g_scores);
    cudaGetSymbolAddress((void**)&gt, g_gate);
    cudaGetSymbolAddress((void**)&up, g_up);
    cudaGetSymbolAddress((void**)&y,  g_y);
    cudaGetSymbolAddress((void**)&rlog, g_rlog);
    cudaGetSymbolAddress((void**)&pw,   g_pairw);
    cudaGetSymbolAddress((void**)&cnt,  g_cnt);
    cudaGetSymbolAddress((void**)&ptok, g_ptok);
    cudaGetSymbolAddress((void**)&ppair,g_ppair);
    cudaGetSymbolAddress((void**)&h_s,  g_h_s);
    cudaGetSymbolAddress((void**)&q_s,  g_q_s);
    cudaGetSymbolAddress((void**)&k_s,  g_k_s);
    cudaGetSymbolAddress((void**)&v_s,  g_v_s);
    cudaGetSymbolAddress((void**)&o_s,  g_o_s);
    cudaGetSymbolAddress((void**)&gts_s,g_gts_s);
    cudaGetSymbolAddress((void**)&sc_s, g_sc_s);
    cudaGetSymbolAddress((void**)&emb_s, g_emb_s);
    cudaGetSymbolAddress((void**)&wq_s,  g_wq_s);
    cudaGetSymbolAddress((void**)&wk_s,  g_wk_s);
    cudaGetSymbolAddress((void**)&wv_s,  g_wv_s);
    cudaGetSymbolAddress((void**)&wo_s,  g_wo_s);
    cudaGetSymbolAddress((void**)&gate_s,g_gate_s);
    cudaGetSymbolAddress((void**)&up_s,  g_up_s);
    cudaGetSymbolAddress((void**)&down_s,g_down_s);

    // ---- pre-split all weights ----
    {
        auto conv = [](const float* in, uint32_t* out, long nElems){
            long nP = nElems/2;
            convert_split<<<(unsigned)(nP/2/256), 256>>>(in, out, nP);
        };
        conv(tok_emb, emb_s, (long)VV*DD);
        conv(wq, wq_s, (long)LL*DD*QD);
        conv(wk, wk_s, (long)LL*DD*KD);
        conv(wv, wv_s, (long)LL*DD*KD);
        conv(wo, wo_s, (long)LL*QD*DD);
        conv(gate_w, gate_s, (long)LL*EE*DD*FF);
        conv(up_w,   up_s,   (long)LL*EE*DD*FF);
        conv(down_w, down_s, (long)LL*EE*FF*DD);
    }

    embed_kernel<<<TT, 256>>>(token_ids, tok_emb, x);

    for (int l = 0; l < LL; l++) {
        // ---- attention ----
        rmsnorm_split<<<TT, 256>>>(x, attn_norm + (long)l*DD, h_s);
        qkv_gemm<<<dim3(12, TT/BM), 256>>>(h_s, wq_s, wk_s, wv_s,
                                           (long)l*DD*QD/2, (long)l*DD*KD/2, (long)l*DD*KD/2,
                                           q, k, v_s);
        qk_rope_split<<<TT*(HH+KVH)/8, 256>>>(q, k, q_s, k_s,
                                              qn + (long)l*HDIM, kn + (long)l*HDIM, pos_ids);
        attn_scores_mma<<<dim3(SS/BN, SS/BM, BB*HH), 256>>>(q_s, k_s, sc);
        softmax_split<<<dim3(SS, BB*HH), 256>>>(sc, sc_s);
        attn_pv_mma<<<dim3(1, SS/BM, BB*HH), 256>>>(sc_s, v_s, o_s);
        mma_gemm<false,true><<<dim3(DD/BN, TT/BM), 256>>>(
            o_s, P_O, 0, QD/2, wo_s, P_WO, (long)l*QD*DD/2, DD/2, x, DD, TT, DD, QD);

        // ---- MoE FFN ----
        rmsnorm_split<<<TT, 256>>>(x, ffn_norm + (long)l*DD, h_s);
        router_kernel<<<TT, 256>>>(h_s, router_w + (long)l*DD*EE, rlog);
        cudaMemsetAsync(cnt, 0, EE * sizeof(int));
        assign_kernel<<<TT/256, 256>>>(rlog, cnt, ptok, ppair, pw);
        moe_gemm<<<dim3(FF/BN, 2*TT/BM, EE), 256>>>(
            h_s, P_H, DD/2, gate_s, P_GATE, (long)l*EE*DD*FF/2, (long)DD*FF/2, FF/2,
            gt, FF, FF, DD, ptok, ppair, cnt);
        moe_gemm<<<dim3(FF/BN, 2*TT/BM, EE), 256>>>(
            h_s, P_H, DD/2, up_s, P_GATE, (long)l*EE*DD*FF/2, (long)DD*FF/2, FF/2,
            up, FF, FF, DD, ptok, ppair, cnt);
        silu_split<<<(2*TT*FF)/1024, 256>>>(gt, up, gts_s);
        moe_gemm<<<dim3(DD/BN, 2*TT/BM, EE), 256>>>(
            gts_s, P_GTS, FF/2, down_s, P_GATE, (long)l*EE*FF*DD/2, (long)FF*DD/2, DD/2,
            y, DD, DD, FF, ppair, ppair, cnt);
        combine_kernel<<<TT, 256>>>(x, y, pw);
    }

    // ---- final norm + tied lm_head ----
    rmsnorm_split<<<TT, 256>>>(x, fin_norm, h_s);
    mma_gemm<true,false><<<dim3(VV/BN, TT/BM), 256>>>(
        h_s, P_H, 0, DD/2, emb_s, P_EMB, 0, DD/2, (float*)d_out, VV, TT, VV, DD);
}